// round 16
// baseline (speedup 1.0000x reference)
#include <cuda_runtime.h>
#include <math.h>
#include <stdint.h>

#define NTOK 8192
#define DDIM 2048
#define NEXP 8

#define BM 128
#define BN 128
#define BK 32
#define KTILES (DDIM / BK)     // 64
#define NTHREADS 128
#define MTILES 20              // 2560 rows/expert = E[cnt] + 12 sigma

#define GATE_BLOCKS (NTOK / 8)             // 1024
#define CONV_BLOCKS 4096
#define N4 (NTOK * DDIM / 4)

// smem geometry (floats) — 3-stage A + 3-stage B
#define AS_STRIDE 36                       // 32 + 4 pad
#define BS_STRIDE 136                      // 128 + 8 pad
#define AS_FLOATS (BM * AS_STRIDE)         // 4608
#define BS_FLOATS (BK * BS_STRIDE)         // 4352
#define OFF_B0    (3 * AS_FLOATS)          // 13824
#define OFF_TOK   (OFF_B0 + 3 * BS_FLOATS) // 26880
#define OFF_W     (OFF_TOK + BM)           // 27008
#define SMEM_FLOATS (OFF_W + BM)           // 27136
#define SMEM_BYTES  (SMEM_FLOATS * 4)      // 108544  -> 2 CTAs/SM

// ---------------------------------------------------------------------------
__device__ int   g_cnt[NEXP];
__device__ int   g_tok[NEXP][NTOK];     // packed: token*2 + slot
__device__ float g_wgt[NEXP][NTOK];
__device__ float g_Xc[(size_t)NTOK * DDIM];      // tf32(RNA)-rounded X
__device__ float g_slot1[(size_t)NTOK * DDIM];   // weighted slot-1 outputs

// ---------------------------------------------------------------------------
__device__ __forceinline__ float to_tf32(float x) {
    float r;
    asm("cvt.rna.tf32.f32 %0, %1;" : "=f"(r) : "f"(x));
    return r;
}
__device__ __forceinline__ uint32_t smem_u32(const void* p) {
    uint32_t a;
    asm("{ .reg .u64 t; cvta.to.shared.u64 t, %1; cvt.u32.u64 %0, t; }" : "=r"(a) : "l"(p));
    return a;
}
#define CP16(dst, src) \
    asm volatile("cp.async.cg.shared.global [%0], [%1], 16;" :: "r"(dst), "l"(src) : "memory")
#define CP_COMMIT() asm volatile("cp.async.commit_group;" ::: "memory")
#define CP_WAIT1()  asm volatile("cp.async.wait_group 1;" ::: "memory")

__device__ __forceinline__ void mma_tf32(float& c0, float& c1, float& c2, float& c3,
                                         float a0, float a1, float a2, float a3,
                                         float b0, float b1) {
    asm volatile(
        "mma.sync.aligned.m16n8k8.row.col.f32.tf32.tf32.f32 "
        "{%0,%1,%2,%3}, {%4,%5,%6,%7}, {%8,%9}, {%0,%1,%2,%3};"
        : "+f"(c0), "+f"(c1), "+f"(c2), "+f"(c3)
        : "r"(__float_as_uint(a0)), "r"(__float_as_uint(a1)),
          "r"(__float_as_uint(a2)), "r"(__float_as_uint(a3)),
          "r"(__float_as_uint(b0)), "r"(__float_as_uint(b1)));
}

// ---------------------------------------------------------------------------
// Fused gating + X->tf32 conversion, role-split by blockIdx.
__global__ __launch_bounds__(256) void gate_conv_kernel(const float* __restrict__ x,
                                                        const float* __restrict__ Wg) {
    if (blockIdx.x >= GATE_BLOCKS) {
        // --- conversion role ---
        int i = (blockIdx.x - GATE_BLOCKS) * 256 + threadIdx.x;
        const float4* s4 = reinterpret_cast<const float4*>(x);
        float4* d4 = reinterpret_cast<float4*>(g_Xc);
#pragma unroll
        for (int it = 0; it < N4 / (CONV_BLOCKS * 256); ++it) {
            float4 v = s4[i];
            v.x = to_tf32(v.x); v.y = to_tf32(v.y);
            v.z = to_tf32(v.z); v.w = to_tf32(v.w);
            d4[i] = v;
            i += CONV_BLOCKS * 256;
        }
        return;
    }

    // --- gating role: one warp per token (scalar FFMA, float4 x loads) ---
    const int warp = threadIdx.x >> 5;
    const int lane = threadIdx.x & 31;
    const int t = blockIdx.x * 8 + warp;

    const float4* row4 = reinterpret_cast<const float4*>(x + (size_t)t * DDIM);
    float acc[8];
#pragma unroll
    for (int e = 0; e < 8; ++e) acc[e] = 0.f;

    for (int i4 = lane; i4 < DDIM / 4; i4 += 32) {
        float4 xq = row4[i4];
        const int k0 = i4 * 4;
#pragma unroll
        for (int j = 0; j < 4; ++j) {
            float xv = (j == 0) ? xq.x : (j == 1) ? xq.y : (j == 2) ? xq.z : xq.w;
            const float4* w4 = reinterpret_cast<const float4*>(Wg + (size_t)(k0 + j) * 8);
            float4 a = w4[0], b = w4[1];
            acc[0] += xv * a.x;  acc[1] += xv * a.y;
            acc[2] += xv * a.z;  acc[3] += xv * a.w;
            acc[4] += xv * b.x;  acc[5] += xv * b.y;
            acc[6] += xv * b.z;  acc[7] += xv * b.w;
        }
    }
#pragma unroll
    for (int off = 16; off > 0; off >>= 1)
#pragma unroll
        for (int e = 0; e < 8; ++e)
            acc[e] += __shfl_xor_sync(0xffffffffu, acc[e], off);

    if (lane == 0) {
        int i0 = 0; float v0 = acc[0];
#pragma unroll
        for (int e = 1; e < 8; ++e)
            if (acc[e] > v0) { v0 = acc[e]; i0 = e; }
        int i1 = -1; float v1 = -INFINITY;
#pragma unroll
        for (int e = 0; e < 8; ++e)
            if (e != i0 && acc[e] > v1) { v1 = acc[e]; i1 = e; }

        float ew = expf(v1 - v0);
        float inv = 1.f / (1.f + ew);
        int p0 = atomicAdd(&g_cnt[i0], 1);
        g_tok[i0][p0] = t * 2;      g_wgt[i0][p0] = inv;
        int p1 = atomicAdd(&g_cnt[i1], 1);
        g_tok[i1][p1] = t * 2 + 1;  g_wgt[i1][p1] = ew * inv;
    }
}

// ---------------------------------------------------------------------------
// TF32 mma.sync gathered expert GEMM. CTA = 128x128, 4 warps (2M x 2N),
// warp tile 64x64, 3-stage cp.async, 2 CTAs/SM.
// Refill interleaved into the ks MMA stream; rotating stage registers.
// Epilogue: slot-0 rows -> out directly; slot-1 rows -> g_slot1.
// ---------------------------------------------------------------------------
__global__ __launch_bounds__(NTHREADS, 2) void expert_gemm(const float* __restrict__ We,
                                                           const float* __restrict__ be,
                                                           float* __restrict__ out) {
    const int e = blockIdx.z;
    const int cnt = g_cnt[e];
    const int m0 = blockIdx.y * BM;
    if (m0 >= cnt) return;
    const int n0 = blockIdx.x * BN;

    extern __shared__ float smem[];
    int*   s_tok = reinterpret_cast<int*>(smem + OFF_TOK);
    float* s_w   = smem + OFF_W;

    const int tid = threadIdx.x;
    const int lane = tid & 31;
    const int wid = tid >> 5;
    const int warp_m = wid >> 1;   // 0..1
    const int warp_n = wid & 1;    // 0..1
    const int lr = lane >> 2;      // 0..7
    const int lc = lane & 3;       // 0..3

    if (tid < BM) {
        int r = m0 + tid;
        if (r < cnt) { s_tok[tid] = g_tok[e][r]; s_w[tid] = g_wgt[e][r]; }
        else         { s_tok[tid] = -1;          s_w[tid] = 0.f; }
    }
    __syncthreads();

    const uint32_t sbase = smem_u32(smem);

    // A: 1024 16B chunks/tile: row = idx>>3, kc = idx&7   (8 per thread)
    uint32_t a_goff[8], a_soff[8];
#pragma unroll
    for (int i = 0; i < 8; ++i) {
        int idx = tid + i * NTHREADS;
        int row = idx >> 3, kc = idx & 7;
        int t2 = s_tok[row];
        int token = (t2 < 0 ? 0 : t2) >> 1;
        a_goff[i] = (uint32_t)token * (DDIM * 4) + kc * 16;
        a_soff[i] = (uint32_t)(row * AS_STRIDE + kc * 4) * 4;
    }
    // B: 1024 chunks/tile: k = idx>>5, nc = idx&31        (8 per thread)
    uint32_t b_goff[8], b_soff[8];
#pragma unroll
    for (int i = 0; i < 8; ++i) {
        int idx = tid + i * NTHREADS;
        int k = idx >> 5, nc = idx & 31;
        b_goff[i] = (uint32_t)k * (DDIM * 4) + nc * 16;
        b_soff[i] = (uint32_t)(OFF_B0 + k * BS_STRIDE + nc * 4) * 4;
    }
    const char* aBase = reinterpret_cast<const char*>(g_Xc);
    const char* bBase = reinterpret_cast<const char*>(We + (size_t)e * DDIM * DDIM + n0);

    // --- prologue: stage tiles 0 and 1 ---
#pragma unroll
    for (int s = 0; s < 2; ++s) {
#pragma unroll
        for (int i = 0; i < 8; ++i)
            CP16(sbase + s * (AS_FLOATS * 4) + a_soff[i], aBase + a_goff[i] + s * (BK * 4));
#pragma unroll
        for (int i = 0; i < 8; ++i)
            CP16(sbase + s * (BS_FLOATS * 4) + b_soff[i], bBase + b_goff[i] + (size_t)s * (BK * DDIM * 4));
        CP_COMMIT();
    }

    float c[4][8][4];
#pragma unroll
    for (int mi = 0; mi < 4; ++mi)
#pragma unroll
        for (int ni = 0; ni < 8; ++ni)
#pragma unroll
            for (int j = 0; j < 4; ++j) c[mi][ni][j] = 0.f;

    const int ar0 = warp_m * 64 + lr;
    const int bc0 = warp_n * 64 + lr;

    // rotating stage offsets (bytes): cur = stage of tile kt, ref = kt+2
    uint32_t aCur = 0, aNxt = AS_FLOATS * 4, aRef = 2 * (AS_FLOATS * 4);
    uint32_t bCur = 0, bNxt = BS_FLOATS * 4, bRef = 2 * (BS_FLOATS * 4);

#pragma unroll 1
    for (int kt = 0; kt < KTILES; ++kt) {
        CP_WAIT1();                 // stage kt resident
        __syncthreads();            // stage-(kt-1) reads done, kt visible

        const float* As = reinterpret_cast<const float*>(
            reinterpret_cast<const char*>(smem) + aCur);
        const float* Bs = smem + (bCur >> 2);   // b_soff carries OFF_B0 for loads below

        const bool doRef = (kt + 2 < KTILES);
        const char* aR = aBase + (kt + 2) * (BK * 4);
        const char* bR = bBase + (size_t)(kt + 2) * (BK * DDIM * 4);

#pragma unroll
        for (int ks = 0; ks < 4; ++ks) {
            const int k0 = ks * 8;
            float av[4][4];
#pragma unroll
            for (int mi = 0; mi < 4; ++mi) {
                const float* ap = As + (ar0 + mi * 16) * AS_STRIDE + k0 + lc;
                av[mi][0] = ap[0];
                av[mi][1] = ap[8 * AS_STRIDE];
                av[mi][2] = ap[4];
                av[mi][3] = ap[8 * AS_STRIDE + 4];
            }
            float bv[8][2];
#pragma unroll
            for (int ni = 0; ni < 8; ++ni) {
                const float* bp = Bs + (OFF_B0 + (k0 + lc) * BS_STRIDE + bc0 + ni * 8);
                bv[ni][0] = bp[0];
                bv[ni][1] = bp[4 * BS_STRIDE];
            }
#pragma unroll
            for (int mi = 0; mi < 4; ++mi)
#pragma unroll
                for (int ni = 0; ni < 8; ++ni)
                    mma_tf32(c[mi][ni][0], c[mi][ni][1], c[mi][ni][2], c[mi][ni][3],
                             av[mi][0], av[mi][1], av[mi][2], av[mi][3],
                             bv[ni][0], bv[ni][1]);

            // interleaved refill: 2 A + 2 B chunks per ks step -> issue hides in MMA shadow
            if (doRef) {
                CP16(sbase + aRef + a_soff[2 * ks],     aR + a_goff[2 * ks]);
                CP16(sbase + aRef + a_soff[2 * ks + 1], aR + a_goff[2 * ks + 1]);
                CP16(sbase + bRef + b_soff[2 * ks],     bR + b_goff[2 * ks]);
                CP16(sbase + bRef + b_soff[2 * ks + 1], bR + b_goff[2 * ks + 1]);
            }
        }
        CP_COMMIT();                // keep group numbering consistent

        // rotate stages
        uint32_t ta = aCur; aCur = aNxt; aNxt = aRef; aRef = ta;
        uint32_t tb = bCur; bCur = bNxt; bNxt = bRef; bRef = tb;
    }

    // --- epilogue: slot 0 -> out, slot 1 -> g_slot1 (weighted, +bias) ---
    const float* brow = be + (size_t)e * DDIM + n0;
#pragma unroll
    for (int mi = 0; mi < 4; ++mi) {
        const int r0 = warp_m * 64 + mi * 16 + lr;
        const int r1 = r0 + 8;
        const int t20 = s_tok[r0];
        const int t21 = s_tok[r1];
        const float w0 = s_w[r0];
        const float w1 = s_w[r1];
        float* dst0;
        float* dst1;
        {
            int tok0 = (t20 < 0 ? 0 : t20) >> 1;
            int tok1 = (t21 < 0 ? 0 : t21) >> 1;
            dst0 = ((t20 & 1) ? g_slot1 : out) + (size_t)tok0 * DDIM + n0;
            dst1 = ((t21 & 1) ? g_slot1 : out) + (size_t)tok1 * DDIM + n0;
        }
#pragma unroll
        for (int ni = 0; ni < 8; ++ni) {
            const int col = warp_n * 64 + ni * 8 + 2 * lc;
            const float bb0 = __ldg(brow + col);
            const float bb1 = __ldg(brow + col + 1);
            if (t20 >= 0) {
                float2 v = make_float2(w0 * (c[mi][ni][0] + bb0),
                                       w0 * (c[mi][ni][1] + bb1));
                *reinterpret_cast<float2*>(dst0 + col) = v;
            }
            if (t21 >= 0) {
                float2 v = make_float2(w1 * (c[mi][ni][2] + bb0),
                                       w1 * (c[mi][ni][3] + bb1));
                *reinterpret_cast<float2*>(dst1 + col) = v;
            }
        }
    }
}

// combine: out[i] += slot1[i]
__global__ __launch_bounds__(256) void combine_kernel(float* __restrict__ out) {
    int i = blockIdx.x * 256 + threadIdx.x;       // over N*D/4
    const float4* s4 = reinterpret_cast<const float4*>(g_slot1);
    float4* o4 = reinterpret_cast<float4*>(out);
    if (i < NTOK * (DDIM / 4)) {
        float4 a = o4[i];
        float4 b = s4[i];
        o4[i] = make_float4(a.x + b.x, a.y + b.y, a.z + b.z, a.w + b.w);
    }
}

// ---------------------------------------------------------------------------
extern "C" void kernel_launch(void* const* d_in, const int* in_sizes, int n_in,
                              void* d_out, int out_size) {
    const float* x  = (const float*)d_in[0];
    const float* Wg = (const float*)d_in[1];
    const float* We = (const float*)d_in[2];
    const float* be = (const float*)d_in[3];
    float* out = (float*)d_out;

    cudaFuncSetAttribute(expert_gemm, cudaFuncAttributeMaxDynamicSharedMemorySize, SMEM_BYTES);

    void* cntPtr;
    cudaGetSymbolAddress(&cntPtr, g_cnt);
    cudaMemsetAsync(cntPtr, 0, NEXP * sizeof(int), 0);

    gate_conv_kernel<<<GATE_BLOCKS + CONV_BLOCKS, 256>>>(x, Wg);

    dim3 grid(DDIM / BN, MTILES, NEXP);
    expert_gemm<<<grid, NTHREADS, SMEM_BYTES>>>(We, be, out);

    combine_kernel<<<(NTOK * DDIM / 4 + 255) / 256, 256>>>(out);
}

// round 17
// speedup vs baseline: 1.1304x; 1.1304x over previous
#include <cuda_runtime.h>
#include <math.h>
#include <stdint.h>

#define NTOK 8192
#define DDIM 2048
#define NEXP 8

#define BM 128
#define BN 128
#define BK 32
#define KTILES (DDIM / BK)     // 64
#define NTHREADS 128
#define MTILES 20              // 2560 rows/expert = E[cnt] + 12 sigma

#define GATE_BLOCKS (NTOK / 8)             // 1024
#define CONV_BLOCKS 4096
#define N4 (NTOK * DDIM / 4)

// smem geometry (floats) — 3-stage A + 3-stage B
#define AS_STRIDE 36                       // 32 + 4 pad
#define BS_STRIDE 136                      // 128 + 8 pad
#define AS_FLOATS (BM * AS_STRIDE)         // 4608
#define BS_FLOATS (BK * BS_STRIDE)         // 4352
#define OFF_B0    (3 * AS_FLOATS)          // 13824
#define OFF_TOK   (OFF_B0 + 3 * BS_FLOATS) // 26880
#define OFF_W     (OFF_TOK + BM)           // 27008
#define SMEM_FLOATS (OFF_W + BM)           // 27136
#define SMEM_BYTES  (SMEM_FLOATS * 4)      // 108544  -> 2 CTAs/SM

// ---------------------------------------------------------------------------
__device__ int   g_cnt[NEXP];
__device__ int   g_tok[NEXP][NTOK];     // packed: token*2 + slot
__device__ float g_wgt[NEXP][NTOK];
__device__ float g_Xc[(size_t)NTOK * DDIM];      // tf32(RNA)-rounded X
__device__ float g_slot1[(size_t)NTOK * DDIM];   // weighted slot-1 outputs

// ---------------------------------------------------------------------------
__device__ __forceinline__ float to_tf32(float x) {
    float r;
    asm("cvt.rna.tf32.f32 %0, %1;" : "=f"(r) : "f"(x));
    return r;
}
__device__ __forceinline__ uint32_t smem_u32(const void* p) {
    uint32_t a;
    asm("{ .reg .u64 t; cvta.to.shared.u64 t, %1; cvt.u32.u64 %0, t; }" : "=r"(a) : "l"(p));
    return a;
}
#define CP16(dst, src) \
    asm volatile("cp.async.cg.shared.global [%0], [%1], 16;" :: "r"(dst), "l"(src) : "memory")
#define CP_COMMIT() asm volatile("cp.async.commit_group;" ::: "memory")
#define CP_WAIT1()  asm volatile("cp.async.wait_group 1;" ::: "memory")

__device__ __forceinline__ void mma_tf32(float& c0, float& c1, float& c2, float& c3,
                                         float a0, float a1, float a2, float a3,
                                         float b0, float b1) {
    asm volatile(
        "mma.sync.aligned.m16n8k8.row.col.f32.tf32.tf32.f32 "
        "{%0,%1,%2,%3}, {%4,%5,%6,%7}, {%8,%9}, {%0,%1,%2,%3};"
        : "+f"(c0), "+f"(c1), "+f"(c2), "+f"(c3)
        : "r"(__float_as_uint(a0)), "r"(__float_as_uint(a1)),
          "r"(__float_as_uint(a2)), "r"(__float_as_uint(a3)),
          "r"(__float_as_uint(b0)), "r"(__float_as_uint(b1)));
}

// ---------------------------------------------------------------------------
// Fused gating + X->tf32 conversion, role-split by blockIdx.
// Gate role: R14 layout — consecutive lanes read consecutive Wg rows (coalesced).
__global__ __launch_bounds__(256) void gate_conv_kernel(const float* __restrict__ x,
                                                        const float* __restrict__ Wg) {
    if (blockIdx.x >= GATE_BLOCKS) {
        // --- conversion role ---
        int i = (blockIdx.x - GATE_BLOCKS) * 256 + threadIdx.x;
        const float4* s4 = reinterpret_cast<const float4*>(x);
        float4* d4 = reinterpret_cast<float4*>(g_Xc);
#pragma unroll
        for (int it = 0; it < N4 / (CONV_BLOCKS * 256); ++it) {
            float4 v = s4[i];
            v.x = to_tf32(v.x); v.y = to_tf32(v.y);
            v.z = to_tf32(v.z); v.w = to_tf32(v.w);
            d4[i] = v;
            i += CONV_BLOCKS * 256;
        }
        return;
    }

    // --- gating role: one warp per token ---
    const int warp = threadIdx.x >> 5;
    const int lane = threadIdx.x & 31;
    const int t = blockIdx.x * 8 + warp;

    const float* row = x + (size_t)t * DDIM;
    float acc[8];
#pragma unroll
    for (int e = 0; e < 8; ++e) acc[e] = 0.f;

    for (int i = lane; i < DDIM; i += 32) {
        float xv = row[i];
        const float4* w4 = reinterpret_cast<const float4*>(Wg + (size_t)i * 8);
        float4 a = w4[0], b = w4[1];
        acc[0] += xv * a.x;  acc[1] += xv * a.y;
        acc[2] += xv * a.z;  acc[3] += xv * a.w;
        acc[4] += xv * b.x;  acc[5] += xv * b.y;
        acc[6] += xv * b.z;  acc[7] += xv * b.w;
    }
#pragma unroll
    for (int off = 16; off > 0; off >>= 1)
#pragma unroll
        for (int e = 0; e < 8; ++e)
            acc[e] += __shfl_xor_sync(0xffffffffu, acc[e], off);

    if (lane == 0) {
        int i0 = 0; float v0 = acc[0];
#pragma unroll
        for (int e = 1; e < 8; ++e)
            if (acc[e] > v0) { v0 = acc[e]; i0 = e; }
        int i1 = -1; float v1 = -INFINITY;
#pragma unroll
        for (int e = 0; e < 8; ++e)
            if (e != i0 && acc[e] > v1) { v1 = acc[e]; i1 = e; }

        float ew = expf(v1 - v0);
        float inv = 1.f / (1.f + ew);
        int p0 = atomicAdd(&g_cnt[i0], 1);
        g_tok[i0][p0] = t * 2;      g_wgt[i0][p0] = inv;
        int p1 = atomicAdd(&g_cnt[i1], 1);
        g_tok[i1][p1] = t * 2 + 1;  g_wgt[i1][p1] = ew * inv;
    }
}

// ---------------------------------------------------------------------------
// TF32 mma.sync gathered expert GEMM. CTA = 128x128, 4 warps (2M x 2N),
// warp tile 64x64, 3-stage cp.async, 2 CTAs/SM.
// Refill interleaved into the ks MMA stream; rotating stage registers.
// Epilogue: slot-0 rows -> out directly; slot-1 rows -> g_slot1.
// ---------------------------------------------------------------------------
__global__ __launch_bounds__(NTHREADS, 2) void expert_gemm(const float* __restrict__ We,
                                                           const float* __restrict__ be,
                                                           float* __restrict__ out) {
    const int e = blockIdx.z;
    const int cnt = g_cnt[e];
    const int m0 = blockIdx.y * BM;
    if (m0 >= cnt) return;
    const int n0 = blockIdx.x * BN;

    extern __shared__ float smem[];
    int*   s_tok = reinterpret_cast<int*>(smem + OFF_TOK);
    float* s_w   = smem + OFF_W;

    const int tid = threadIdx.x;
    const int lane = tid & 31;
    const int wid = tid >> 5;
    const int warp_m = wid >> 1;   // 0..1
    const int warp_n = wid & 1;    // 0..1
    const int lr = lane >> 2;      // 0..7
    const int lc = lane & 3;       // 0..3

    if (tid < BM) {
        int r = m0 + tid;
        if (r < cnt) { s_tok[tid] = g_tok[e][r]; s_w[tid] = g_wgt[e][r]; }
        else         { s_tok[tid] = -1;          s_w[tid] = 0.f; }
    }
    __syncthreads();

    const uint32_t sbase = smem_u32(smem);

    // A: 1024 16B chunks/tile: row = idx>>3, kc = idx&7   (8 per thread)
    uint32_t a_goff[8], a_soff[8];
#pragma unroll
    for (int i = 0; i < 8; ++i) {
        int idx = tid + i * NTHREADS;
        int row = idx >> 3, kc = idx & 7;
        int t2 = s_tok[row];
        int token = (t2 < 0 ? 0 : t2) >> 1;
        a_goff[i] = (uint32_t)token * (DDIM * 4) + kc * 16;
        a_soff[i] = (uint32_t)(row * AS_STRIDE + kc * 4) * 4;
    }
    // B: 1024 chunks/tile: k = idx>>5, nc = idx&31        (8 per thread)
    uint32_t b_goff[8], b_soff[8];
#pragma unroll
    for (int i = 0; i < 8; ++i) {
        int idx = tid + i * NTHREADS;
        int k = idx >> 5, nc = idx & 31;
        b_goff[i] = (uint32_t)k * (DDIM * 4) + nc * 16;
        b_soff[i] = (uint32_t)(OFF_B0 + k * BS_STRIDE + nc * 4) * 4;
    }
    const char* aBase = reinterpret_cast<const char*>(g_Xc);
    const char* bBase = reinterpret_cast<const char*>(We + (size_t)e * DDIM * DDIM + n0);

    // --- prologue: stage tiles 0 and 1 ---
#pragma unroll
    for (int s = 0; s < 2; ++s) {
#pragma unroll
        for (int i = 0; i < 8; ++i)
            CP16(sbase + s * (AS_FLOATS * 4) + a_soff[i], aBase + a_goff[i] + s * (BK * 4));
#pragma unroll
        for (int i = 0; i < 8; ++i)
            CP16(sbase + s * (BS_FLOATS * 4) + b_soff[i], bBase + b_goff[i] + (size_t)s * (BK * DDIM * 4));
        CP_COMMIT();
    }

    float c[4][8][4];
#pragma unroll
    for (int mi = 0; mi < 4; ++mi)
#pragma unroll
        for (int ni = 0; ni < 8; ++ni)
#pragma unroll
            for (int j = 0; j < 4; ++j) c[mi][ni][j] = 0.f;

    const int ar0 = warp_m * 64 + lr;
    const int bc0 = warp_n * 64 + lr;

    // rotating stage offsets (bytes): cur = stage of tile kt, ref = kt+2
    uint32_t aCur = 0, aNxt = AS_FLOATS * 4, aRef = 2 * (AS_FLOATS * 4);
    uint32_t bCur = 0, bNxt = BS_FLOATS * 4, bRef = 2 * (BS_FLOATS * 4);

#pragma unroll 1
    for (int kt = 0; kt < KTILES; ++kt) {
        CP_WAIT1();                 // stage kt resident
        __syncthreads();            // stage-(kt-1) reads done, kt visible

        const float* As = reinterpret_cast<const float*>(
            reinterpret_cast<const char*>(smem) + aCur);
        const float* Bs = smem + (bCur >> 2);   // b_soff carries OFF_B0 for loads below

        const bool doRef = (kt + 2 < KTILES);
        const char* aR = aBase + (kt + 2) * (BK * 4);
        const char* bR = bBase + (size_t)(kt + 2) * (BK * DDIM * 4);

#pragma unroll
        for (int ks = 0; ks < 4; ++ks) {
            const int k0 = ks * 8;
            float av[4][4];
#pragma unroll
            for (int mi = 0; mi < 4; ++mi) {
                const float* ap = As + (ar0 + mi * 16) * AS_STRIDE + k0 + lc;
                av[mi][0] = ap[0];
                av[mi][1] = ap[8 * AS_STRIDE];
                av[mi][2] = ap[4];
                av[mi][3] = ap[8 * AS_STRIDE + 4];
            }
            float bv[8][2];
#pragma unroll
            for (int ni = 0; ni < 8; ++ni) {
                const float* bp = Bs + (OFF_B0 + (k0 + lc) * BS_STRIDE + bc0 + ni * 8);
                bv[ni][0] = bp[0];
                bv[ni][1] = bp[4 * BS_STRIDE];
            }
#pragma unroll
            for (int mi = 0; mi < 4; ++mi)
#pragma unroll
                for (int ni = 0; ni < 8; ++ni)
                    mma_tf32(c[mi][ni][0], c[mi][ni][1], c[mi][ni][2], c[mi][ni][3],
                             av[mi][0], av[mi][1], av[mi][2], av[mi][3],
                             bv[ni][0], bv[ni][1]);

            // interleaved refill: 2 A + 2 B chunks per ks step -> issue hides in MMA shadow
            if (doRef) {
                CP16(sbase + aRef + a_soff[2 * ks],     aR + a_goff[2 * ks]);
                CP16(sbase + aRef + a_soff[2 * ks + 1], aR + a_goff[2 * ks + 1]);
                CP16(sbase + bRef + b_soff[2 * ks],     bR + b_goff[2 * ks]);
                CP16(sbase + bRef + b_soff[2 * ks + 1], bR + b_goff[2 * ks + 1]);
            }
        }
        CP_COMMIT();                // keep group numbering consistent

        // rotate stages
        uint32_t ta = aCur; aCur = aNxt; aNxt = aRef; aRef = ta;
        uint32_t tb = bCur; bCur = bNxt; bNxt = bRef; bRef = tb;
    }

    // --- epilogue: slot 0 -> out, slot 1 -> g_slot1 (weighted, +bias) ---
    const float* brow = be + (size_t)e * DDIM + n0;
#pragma unroll
    for (int mi = 0; mi < 4; ++mi) {
        const int r0 = warp_m * 64 + mi * 16 + lr;
        const int r1 = r0 + 8;
        const int t20 = s_tok[r0];
        const int t21 = s_tok[r1];
        const float w0 = s_w[r0];
        const float w1 = s_w[r1];
        float* dst0;
        float* dst1;
        {
            int tok0 = (t20 < 0 ? 0 : t20) >> 1;
            int tok1 = (t21 < 0 ? 0 : t21) >> 1;
            dst0 = ((t20 & 1) ? g_slot1 : out) + (size_t)tok0 * DDIM + n0;
            dst1 = ((t21 & 1) ? g_slot1 : out) + (size_t)tok1 * DDIM + n0;
        }
#pragma unroll
        for (int ni = 0; ni < 8; ++ni) {
            const int col = warp_n * 64 + ni * 8 + 2 * lc;
            const float bb0 = __ldg(brow + col);
            const float bb1 = __ldg(brow + col + 1);
            if (t20 >= 0) {
                float2 v = make_float2(w0 * (c[mi][ni][0] + bb0),
                                       w0 * (c[mi][ni][1] + bb1));
                *reinterpret_cast<float2*>(dst0 + col) = v;
            }
            if (t21 >= 0) {
                float2 v = make_float2(w1 * (c[mi][ni][2] + bb0),
                                       w1 * (c[mi][ni][3] + bb1));
                *reinterpret_cast<float2*>(dst1 + col) = v;
            }
        }
    }
}

// combine: out[i] += slot1[i]
__global__ __launch_bounds__(256) void combine_kernel(float* __restrict__ out) {
    int i = blockIdx.x * 256 + threadIdx.x;       // over N*D/4
    const float4* s4 = reinterpret_cast<const float4*>(g_slot1);
    float4* o4 = reinterpret_cast<float4*>(out);
    if (i < NTOK * (DDIM / 4)) {
        float4 a = o4[i];
        float4 b = s4[i];
        o4[i] = make_float4(a.x + b.x, a.y + b.y, a.z + b.z, a.w + b.w);
    }
}

// ---------------------------------------------------------------------------
extern "C" void kernel_launch(void* const* d_in, const int* in_sizes, int n_in,
                              void* d_out, int out_size) {
    const float* x  = (const float*)d_in[0];
    const float* Wg = (const float*)d_in[1];
    const float* We = (const float*)d_in[2];
    const float* be = (const float*)d_in[3];
    float* out = (float*)d_out;

    cudaFuncSetAttribute(expert_gemm, cudaFuncAttributeMaxDynamicSharedMemorySize, SMEM_BYTES);

    void* cntPtr;
    cudaGetSymbolAddress(&cntPtr, g_cnt);
    cudaMemsetAsync(cntPtr, 0, NEXP * sizeof(int), 0);

    gate_conv_kernel<<<GATE_BLOCKS + CONV_BLOCKS, 256>>>(x, Wg);

    dim3 grid(DDIM / BN, MTILES, NEXP);
    expert_gemm<<<grid, NTHREADS, SMEM_BYTES>>>(We, be, out);

    combine_kernel<<<(NTOK * DDIM / 4 + 255) / 256, 256>>>(out);
}